// round 4
// baseline (speedup 1.0000x reference)
#include <cuda_runtime.h>
#include <cstdint>

#define B_    8
#define CIN   320
#define COUT  320
#define H_    64
#define W_    64
#define KTOT  2880      // 9 taps * 320 ci   (k = tap*320 + ci, tap = kh*3+kw)
#define BM    160
#define BK    64        // bytes of K per stage (2 x k32 mma steps)
#define NKI   45        // KTOT / BK
#define S_    2         // h-rows per CTA sharing the A (weight) tile
#define NTH   320

// __device__ scratch (no runtime allocation allowed)
__device__ __align__(16) int8_t g_x8[(size_t)B_ * H_ * W_ * CIN];   // NHWC int8 acts (10.5MB)
__device__ __align__(16) int8_t g_w8[(size_t)COUT * KTOT];          // reordered int8 weights
__device__ float g_off[COUT * 9];                                   // bias - scale*zp*corr table

// ---------------- helpers ----------------
__device__ __forceinline__ void cp_async16(uint32_t dst, const void* src, int nbytes) {
    asm volatile("cp.async.cg.shared.global [%0], [%1], 16, %2;\n"
                 :: "r"(dst), "l"(src), "r"(nbytes));
}
__device__ __forceinline__ void ldsm_x4(uint32_t* r, uint32_t addr) {
    asm volatile("ldmatrix.sync.aligned.m8n8.x4.shared.b16 {%0,%1,%2,%3}, [%4];"
                 : "=r"(r[0]), "=r"(r[1]), "=r"(r[2]), "=r"(r[3]) : "r"(addr));
}
__device__ __forceinline__ void ldsm_x2(uint32_t* r, uint32_t addr) {
    asm volatile("ldmatrix.sync.aligned.m8n8.x2.shared.b16 {%0,%1}, [%2];"
                 : "=r"(r[0]), "=r"(r[1]) : "r"(addr));
}
__device__ __forceinline__ void imma(int* d, const uint32_t* a, const uint32_t* b) {
    asm volatile("mma.sync.aligned.m16n8k32.row.col.s32.s8.s8.s32 "
                 "{%0,%1,%2,%3}, {%4,%5,%6,%7}, {%8,%9}, {%0,%1,%2,%3};"
                 : "+r"(d[0]), "+r"(d[1]), "+r"(d[2]), "+r"(d[3])
                 : "r"(a[0]), "r"(a[1]), "r"(a[2]), "r"(a[3]), "r"(b[0]), "r"(b[1]));
}

// ---------------- Prep 1: quantize f32 NCHW -> int8 NHWC ----------------
// grid (B*H, CIN/64), 256 threads; smem transpose tile 64(w) x 64(ci)
__global__ void quant_nhwc_kernel(const float* __restrict__ x,
                                  const float* __restrict__ inv_p,
                                  const float* __restrict__ zp_p)
{
    __shared__ int8_t t[64][68];
    const float inv = inv_p[0];
    const float zp  = zp_p[0];
    const int tid = threadIdx.x;
    const int bh  = blockIdx.x;            // b*64 + h
    const int b   = bh >> 6, h = bh & 63;
    const int ci0 = blockIdx.y * 64;

    const int w = tid & 63;
    const int cq = tid >> 6;               // 0..3
    #pragma unroll
    for (int i = 0; i < 16; i++) {
        int ci = i * 4 + cq;
        float v = x[(((size_t)b * CIN + ci0 + ci) * H_ + h) * W_ + w];
        float q = fminf(fmaxf(rintf(v * inv) + zp, -128.f), 127.f);
        t[w][ci] = (int8_t)__float2int_rn(q);
    }
    __syncthreads();

    const int c4 = (tid & 15) * 4;
    #pragma unroll
    for (int i = 0; i < 4; i++) {
        int ww = i * 16 + (tid >> 4);
        uint32_t v = *reinterpret_cast<const uint32_t*>(&t[ww][c4]);
        *reinterpret_cast<uint32_t*>(
            g_x8 + ((size_t)bh * W_ + ww) * CIN + ci0 + c4) = v;
    }
}

// ---------------- Prep 2: weights i32 [O][Ci][3][3] -> int8 [O][tap][Ci] ----------------
__global__ void wreorder_kernel(const int* __restrict__ w)
{
    const int o  = blockIdx.x;
    const int ci = threadIdx.x;
    const int* src = w + ((size_t)o * CIN + ci) * 9;
    int8_t* dst = g_w8 + (size_t)o * KTOT + ci;
    #pragma unroll
    for (int j = 0; j < 9; j++)
        dst[j * CIN] = (int8_t)src[j];
}

// ---------------- Prep 3: OFF table ----------------
// OFF[o][hc*3+wc] = bias[o] - scale[o]*zp * sum_{kh in rows(hc), kw in cols(wc)} wsum[o][kh][kw]
__global__ void off_kernel(const float* __restrict__ wsum,
                           const float* __restrict__ scale,
                           const float* __restrict__ bias,
                           const float* __restrict__ zp_p)
{
    const int o = threadIdx.x;
    const float zp = zp_p[0];
    float ws[9];
    #pragma unroll
    for (int j = 0; j < 9; j++) ws[j] = wsum[o * 9 + j];
    #pragma unroll
    for (int hc = 0; hc < 3; hc++) {
        #pragma unroll
        for (int wc = 0; wc < 3; wc++) {
            float s = 0.f;
            #pragma unroll
            for (int kh = 0; kh < 3; kh++) {
                if ((hc == 0 && kh == 0) || (hc == 2 && kh == 2)) continue;
                #pragma unroll
                for (int kw = 0; kw < 3; kw++) {
                    if ((wc == 0 && kw == 0) || (wc == 2 && kw == 2)) continue;
                    s += ws[kh * 3 + kw];
                }
            }
            g_off[o * 9 + hc * 3 + wc] = bias[o] - scale[o] * zp * s;
        }
    }
}

// ---------------- Main int8 IMMA implicit-GEMM conv ----------------
// M=320 (2 tiles of 160), per CTA: S_=2 h-rows x 64 w (N=64 per row), K=2880.
// 10 warps (5x2), warp tile 32x32 per s. smem rows 80B stride (conflict-free ldmatrix).
static constexpr int A_ROWB = 80;
static constexpr int A_STG  = BM * A_ROWB;        // 12800
static constexpr int B_STG  = S_ * 64 * A_ROWB;   // 10240
static constexpr int STG    = A_STG + B_STG;      // 23040

__global__ __launch_bounds__(NTH, 2)
void conv_imma_kernel(const float* __restrict__ scale,
                      float* __restrict__ out)
{
    __shared__ __align__(16) unsigned char sm[2 * STG];
    const uint32_t smb = (uint32_t)__cvta_generic_to_shared(sm);

    const int tid  = threadIdx.x;
    const int warp = tid >> 5;
    const int lane = tid & 31;
    const int wm   = (warp >> 1) * 32;
    const int wn   = (warp & 1) * 32;

    const int b  = blockIdx.x >> 5;
    const int hg = (blockIdx.x & 31) * S_;
    const int m0 = blockIdx.y * BM;

    int acc[S_][2][4][4];
    #pragma unroll
    for (int s = 0; s < S_; s++)
        #pragma unroll
        for (int mt = 0; mt < 2; mt++)
            #pragma unroll
            for (int nt = 0; nt < 4; nt++)
                #pragma unroll
                for (int r = 0; r < 4; r++)
                    acc[s][mt][nt][r] = 0;

    auto load_stage = [&](int it, int buf) {
        const int kb  = it * BK;
        const int tap = kb / 320;
        const int ci0 = kb - tap * 320;
        const int kh  = tap / 3;
        const int kw  = tap - kh * 3;
        const uint32_t base = smb + buf * STG;
        // A: 160 rows x 64B (4 x 16B)
        #pragma unroll
        for (int t = 0; t < 2; t++) {
            int idx = tid + t * NTH;        // 0..639
            int row = idx >> 2, vec = idx & 3;
            const void* src = g_w8 + (size_t)(m0 + row) * KTOT + kb + vec * 16;
            cp_async16(base + row * A_ROWB + vec * 16, src, 16);
        }
        // B: S_*64 rows x 64B  (512 x 16B chunks)
        #pragma unroll
        for (int t = 0; t < 2; t++) {
            int idx = tid + t * NTH;
            if (idx < 512) {
                int ridx = idx >> 2, vec = idx & 3;
                int s = ridx >> 6, n = ridx & 63;
                int ih = hg + s + kh - 1;
                int iw = n + kw - 1;
                bool ok = ((unsigned)ih < (unsigned)H_) && ((unsigned)iw < (unsigned)W_);
                int ihc = ok ? ih : 0, iwc = ok ? iw : 0;
                const void* src = g_x8 +
                    (((size_t)b * H_ + ihc) * W_ + iwc) * CIN + ci0 + vec * 16;
                cp_async16(base + A_STG + (s * 64 + n) * A_ROWB + vec * 16,
                           src, ok ? 16 : 0);
            }
        }
        asm volatile("cp.async.commit_group;\n" ::: "memory");
    };

    load_stage(0, 0);

    // per-lane ldmatrix address components
    const uint32_t a_row  = wm + (lane & 15);
    const uint32_t a_byte = (lane >> 4) * 16;
    const uint32_t b_row  = wn + (lane & 7);
    const uint32_t b_byte = ((lane >> 3) & 1) * 16;

    for (int it = 0; it < NKI; it++) {
        const int buf = it & 1;
        asm volatile("cp.async.wait_group 0;\n" ::: "memory");
        __syncthreads();
        if (it + 1 < NKI) load_stage(it + 1, buf ^ 1);

        const uint32_t Ab = smb + buf * STG;
        const uint32_t Bb = Ab + A_STG;
        #pragma unroll
        for (int ks = 0; ks < 2; ks++) {
            uint32_t a[2][4];
            #pragma unroll
            for (int mt = 0; mt < 2; mt++)
                ldsm_x4(a[mt], Ab + (a_row + mt * 16) * A_ROWB + a_byte + ks * 32);
            #pragma unroll
            for (int s = 0; s < S_; s++) {
                #pragma unroll
                for (int nt = 0; nt < 4; nt++) {
                    uint32_t bfrag[2];
                    ldsm_x2(bfrag, Bb + (s * 64 + b_row + nt * 8) * A_ROWB
                                      + b_byte + ks * 32);
                    imma(acc[s][0][nt], a[0], bfrag);
                    imma(acc[s][1][nt], a[1], bfrag);
                }
            }
        }
    }

    // ---------------- epilogue ----------------
    #pragma unroll
    for (int s = 0; s < S_; s++) {
        const int h  = hg + s;
        const int hc = (h == 0) ? 0 : ((h == H_ - 1) ? 2 : 1);
        #pragma unroll
        for (int mt = 0; mt < 2; mt++) {
            const int o = m0 + wm + mt * 16 + (lane >> 2);
            const float sc0 = scale[o];
            const float sc1 = scale[o + 8];
            const float* of0 = g_off + o * 9 + hc * 3;
            const float* of1 = g_off + (o + 8) * 9 + hc * 3;
            #pragma unroll
            for (int nt = 0; nt < 4; nt++) {
                const int w = wn + nt * 8 + (lane & 3) * 2;
                const int wc0 = (w == 0) ? 0 : 1;
                const int wc1 = (w + 1 == W_ - 1) ? 2 : 1;
                float2 v0, v1;
                v0.x = sc0 * (float)acc[s][mt][nt][0] + of0[wc0];
                v0.y = sc0 * (float)acc[s][mt][nt][1] + of0[wc1];
                v1.x = sc1 * (float)acc[s][mt][nt][2] + of1[wc0];
                v1.y = sc1 * (float)acc[s][mt][nt][3] + of1[wc1];
                size_t p0 = (((size_t)b * COUT + o) * H_ + h) * W_ + w;
                size_t p1 = (((size_t)b * COUT + o + 8) * H_ + h) * W_ + w;
                *reinterpret_cast<float2*>(out + p0) = v0;
                *reinterpret_cast<float2*>(out + p1) = v1;
            }
        }
    }
}

// ---------------- Launch ----------------
// Inputs: 0:x f32 [8,320,64,64]  1:weight_int i32 [320,320,3,3]
//         2:weight_sum_by_input_channels f32 [320,1,3,3]  3:scale f32 [320]
//         4:act_scales_inv f32 [1]  5:act_zero_points f32 [1]  6:bias f32 [320]
// Output: f32 [8,320,64,64]
extern "C" void kernel_launch(void* const* d_in, const int* in_sizes, int n_in,
                              void* d_out, int out_size)
{
    const float* x    = (const float*)d_in[0];
    const int*   wint = (const int*)  d_in[1];
    const float* wsum = (const float*)d_in[2];
    const float* scl  = (const float*)d_in[3];
    const float* inv  = (const float*)d_in[4];
    const float* zp   = (const float*)d_in[5];
    const float* bias = (const float*)d_in[6];
    float* out = (float*)d_out;

    {   // quantize + NHWC transpose
        dim3 grid(B_ * H_, CIN / 64);
        quant_nhwc_kernel<<<grid, 256>>>(x, inv, zp);
    }
    {   // weight reorder -> int8 [O][tap][ci]
        wreorder_kernel<<<COUT, CIN>>>(wint);
    }
    {   // epilogue offset table
        off_kernel<<<1, COUT>>>(wsum, scl, bias, zp);
    }
    {   // int8 IMMA implicit GEMM
        dim3 grid(B_ * (H_ / S_), COUT / BM);   // (256, 2)
        conv_imma_kernel<<<grid, NTH>>>(scl, out);
    }
}

// round 7
// speedup vs baseline: 2.6545x; 2.6545x over previous
#include <cuda_runtime.h>
#include <cuda_fp16.h>
#include <cstdint>

#define B_    8
#define CIN   320
#define COUT  320
#define H_    64
#define W_    64
#define KTOT  2880      // 9 taps * 320 ci ;  k = tap*320 + ci  (tap-major)
#define BM    160
#define BK    64        // k per stage (4 mma k16 steps); tap constant per stage
#define NKI   45        // KTOT / BK
#define S_    2         // h rows per CTA
#define NTH   320

// __device__ scratch
__device__ __align__(16) __half g_xq3[(size_t)B_ * CIN * H_ * 3 * W_]; // pre-shifted acts fp16
__device__ __align__(16) __half g_wh[(size_t)COUT * KTOT];             // weights fp16 [o][tap][ci]

// ---------------- helpers ----------------
__device__ __forceinline__ void cp_async16(uint32_t dst, const void* src, int nbytes) {
    asm volatile("cp.async.cg.shared.global [%0], [%1], 16, %2;\n"
                 :: "r"(dst), "l"(src), "r"(nbytes));
}
__device__ __forceinline__ void ldsm_x4(uint32_t* r, uint32_t addr) {
    asm volatile("ldmatrix.sync.aligned.m8n8.x4.shared.b16 {%0,%1,%2,%3}, [%4];"
                 : "=r"(r[0]), "=r"(r[1]), "=r"(r[2]), "=r"(r[3]) : "r"(addr));
}
__device__ __forceinline__ void ldsm_x4t(uint32_t* r, uint32_t addr) {
    asm volatile("ldmatrix.sync.aligned.m8n8.x4.trans.shared.b16 {%0,%1,%2,%3}, [%4];"
                 : "=r"(r[0]), "=r"(r[1]), "=r"(r[2]), "=r"(r[3]) : "r"(addr));
}
__device__ __forceinline__ void hmma(float* d, const uint32_t* a, const uint32_t* b) {
    asm volatile("mma.sync.aligned.m16n8k16.row.col.f32.f16.f16.f32 "
                 "{%0,%1,%2,%3}, {%4,%5,%6,%7}, {%8,%9}, {%0,%1,%2,%3};"
                 : "+f"(d[0]), "+f"(d[1]), "+f"(d[2]), "+f"(d[3])
                 : "r"(a[0]), "r"(a[1]), "r"(a[2]), "r"(a[3]), "r"(b[0]), "r"(b[1]));
}

// ---------------- Prep 1: quantize + 3-shift (fp16), one warp per (b,ci,h) row --------
__global__ void quant_kernel(const float* __restrict__ x,
                             const float* __restrict__ inv_p,
                             const float* __restrict__ zp_p)
{
    const float inv = inv_p[0];
    const float zp  = zp_p[0];
    int warp = (blockIdx.x * blockDim.x + threadIdx.x) >> 5;
    int lane = threadIdx.x & 31;
    if (warp >= B_ * CIN * H_) return;

    float2 v = reinterpret_cast<const float2*>(x + (size_t)warp * W_)[lane];
    float r0 = fminf(fmaxf(rintf(v.x * inv) + zp, -128.f), 127.f) - zp;
    float r1 = fminf(fmaxf(rintf(v.y * inv) + zp, -128.f), 127.f) - zp;
    __half2 h01 = __floats2half2_rn(r0, r1);
    uint32_t r = *reinterpret_cast<uint32_t*>(&h01);

    uint32_t prev = __shfl_up_sync(0xffffffffu, r, 1);
    uint32_t next = __shfl_down_sync(0xffffffffu, r, 1);
    if (lane == 0)  prev = 0;
    if (lane == 31) next = 0;
    uint32_t v0 = (prev >> 16) | (r << 16);   // kw=0 shift: pos n holds x[n-1]
    uint32_t v2 = (r >> 16) | (next << 16);   // kw=2 shift: pos n holds x[n+1]

    uint32_t* g32 = reinterpret_cast<uint32_t*>(g_xq3);
    size_t base = (size_t)warp * 96 + lane;
    g32[base]      = v0;
    g32[base + 32] = r;
    g32[base + 64] = v2;
}

// ---------------- Prep 2: weights i32 [O][Ci][3][3] -> fp16 [O][tap][Ci] -------------
__global__ void wreorder_kernel(const int* __restrict__ w)
{
    const int o  = blockIdx.x;
    const int ci = threadIdx.x;
    const int* src = w + ((size_t)o * CIN + ci) * 9;
    __half* dst = g_wh + (size_t)o * KTOT + ci;
    #pragma unroll
    for (int tap = 0; tap < 9; tap++)
        dst[tap * CIN] = __int2half_rn(src[tap]);
}

// ---------------- Main fp16 HMMA implicit-GEMM conv ----------------
static constexpr int ROWB  = 144;
static constexpr int A_STG = BM * ROWB;          // 23040
static constexpr int SUB_B = 64 * ROWB;          // 9216
static constexpr int B_STG = S_ * SUB_B;         // 18432
static constexpr int STG   = A_STG + B_STG;      // 41472
static constexpr int SMEM_TOTAL = 2 * STG;       // 82944

__global__ __launch_bounds__(NTH, 2)
void conv_hmma_kernel(const float* __restrict__ scale,
                      const float* __restrict__ bias,
                      float* __restrict__ out)
{
    extern __shared__ __align__(16) unsigned char sm[];
    const uint32_t smb = (uint32_t)__cvta_generic_to_shared(sm);

    const int tid  = threadIdx.x;
    const int warp = tid >> 5;             // 0..9
    const int lane = tid & 31;
    const int wm   = (warp >> 1) * 32;     // 0..128
    const int ws   = warp & 1;             // h sub-tile

    const int b  = blockIdx.x >> 5;
    const int hg = (blockIdx.x & 31) * S_;
    const int m0 = blockIdx.y * BM;

    float acc[2][8][4];
    #pragma unroll
    for (int mt = 0; mt < 2; mt++)
        #pragma unroll
        for (int nt = 0; nt < 8; nt++)
            #pragma unroll
            for (int r = 0; r < 4; r++)
                acc[mt][nt][r] = 0.f;

    auto load_stage = [&](int it, int buf) {
        const int kb  = it * BK;
        const int tap = kb / 320;
        const int cib = kb - tap * 320;
        const int kh  = tap / 3;
        const int kw  = tap - kh * 3;
        const uint32_t base = smb + buf * STG;
        // A: 160 rows x 128B  (1280 x 16B)
        #pragma unroll
        for (int t = 0; t < 4; t++) {
            int idx = tid + t * NTH;
            int row = idx >> 3, vec = idx & 7;
            const void* src = g_wh + (size_t)(m0 + row) * KTOT + kb + vec * 8;
            cp_async16(base + row * ROWB + vec * 16, src, 16);
        }
        // B: 2 sub x 64 k-rows x 128B (1024 x 16B)
        #pragma unroll
        for (int t = 0; t < 4; t++) {
            int idx = tid + t * NTH;
            if (idx < 1024) {
                int ridx = idx >> 3, vec = idx & 7;
                int s = ridx >> 6, k = ridx & 63;
                int ci = cib + k;
                int ih = hg + s + kh - 1;
                int ok = ((unsigned)ih < (unsigned)H_) ? 16 : 0;
                if (!ok) ih = 0;
                const void* src = g_xq3 +
                    ((((size_t)b * CIN + ci) * H_ + ih) * 3 + kw) * W_ + vec * 8;
                cp_async16(base + A_STG + (s * 64 + k) * ROWB + vec * 16, src, ok);
            }
        }
        asm volatile("cp.async.commit_group;\n" ::: "memory");
    };

    load_stage(0, 0);

    const uint32_t a_row  = wm + (lane & 15);
    const uint32_t a_byte = (lane >> 4) * 16;
    const uint32_t b_krow = lane & 15;
    const uint32_t b_nby  = (lane >> 4) * 16;

    for (int it = 0; it < NKI; it++) {
        const int buf = it & 1;
        asm volatile("cp.async.wait_group 0;\n" ::: "memory");
        __syncthreads();
        if (it + 1 < NKI) load_stage(it + 1, buf ^ 1);

        const uint32_t Ab = smb + buf * STG;
        const uint32_t Bb = Ab + A_STG + ws * SUB_B;
        #pragma unroll
        for (int ks = 0; ks < 4; ks++) {
            uint32_t a[2][4];
            #pragma unroll
            for (int mt = 0; mt < 2; mt++)
                ldsm_x4(a[mt], Ab + (a_row + mt * 16) * ROWB + ks * 32 + a_byte);
            #pragma unroll
            for (int ng = 0; ng < 4; ng++) {
                uint32_t bfrag[4];
                ldsm_x4t(bfrag, Bb + (ks * 16 + b_krow) * ROWB + ng * 32 + b_nby);
                #pragma unroll
                for (int mt = 0; mt < 2; mt++) {
                    hmma(acc[mt][ng * 2 + 0], a[mt], bfrag + 0);
                    hmma(acc[mt][ng * 2 + 1], a[mt], bfrag + 2);
                }
            }
        }
    }

    // ---------------- epilogue (direct fragment -> gmem) ----------------
    // x is pre-shifted (zero-point already removed, padding = 0), so
    // out = scale[o] * acc + bias[o]  -- no further zp correction.
    const int h = hg + ws;
    #pragma unroll
    for (int mt = 0; mt < 2; mt++) {
        const int o0 = m0 + wm + mt * 16 + (lane >> 2);
        const int o1 = o0 + 8;
        const float sc0 = scale[o0];
        const float sc1 = scale[o1];
        const float bb0 = bias[o0];
        const float bb1 = bias[o1];
        #pragma unroll
        for (int nt = 0; nt < 8; nt++) {
            const int w = nt * 8 + (lane & 3) * 2;
            float2 v0, v1;
            v0.x = sc0 * acc[mt][nt][0] + bb0;
            v0.y = sc0 * acc[mt][nt][1] + bb0;
            v1.x = sc1 * acc[mt][nt][2] + bb1;
            v1.y = sc1 * acc[mt][nt][3] + bb1;
            size_t p0 = (((size_t)b * COUT + o0) * H_ + h) * W_ + w;
            size_t p1 = (((size_t)b * COUT + o1) * H_ + h) * W_ + w;
            *reinterpret_cast<float2*>(out + p0) = v0;
            *reinterpret_cast<float2*>(out + p1) = v1;
        }
    }
}

// ---------------- Launch ----------------
// Inputs: 0:x f32  1:weight_int i32  2:weight_sum f32 (unused)  3:scale f32
//         4:act_scales_inv f32  5:act_zero_points f32  6:bias f32 ; out f32
extern "C" void kernel_launch(void* const* d_in, const int* in_sizes, int n_in,
                              void* d_out, int out_size)
{
    const float* x    = (const float*)d_in[0];
    const int*   wint = (const int*)  d_in[1];
    const float* scl  = (const float*)d_in[3];
    const float* inv  = (const float*)d_in[4];
    const float* zp   = (const float*)d_in[5];
    const float* bias = (const float*)d_in[6];
    float* out = (float*)d_out;

    cudaFuncSetAttribute(conv_hmma_kernel,
                         cudaFuncAttributeMaxDynamicSharedMemorySize, SMEM_TOTAL);

    {   // quantize + pre-shift
        int rows = B_ * CIN * H_;
        quant_kernel<<<rows / 8, 256>>>(x, inv, zp);
    }
    {   // weights -> fp16, tap-major reorder
        wreorder_kernel<<<COUT, CIN>>>(wint);
    }
    {   // fp16 HMMA implicit GEMM
        dim3 grid(B_ * (H_ / S_), COUT / BM);   // (256, 2)
        conv_hmma_kernel<<<grid, NTH, SMEM_TOTAL>>>(scl, bias, out);
    }
}

// round 8
// speedup vs baseline: 2.7778x; 1.0465x over previous
#include <cuda_runtime.h>
#include <cuda_fp16.h>
#include <cstdint>

#define B_    8
#define CIN   320
#define COUT  320
#define H_    64
#define W_    64
#define KTOT  2880      // k = tap*320 + ci (tap-major)
#define BM    320       // full M per CTA
#define BK    64        // 4 mma k16 steps per stage; tap constant per stage
#define NKI   45        // KTOT / BK
#define S_    2         // h rows per CTA (BN = 128)
#define NTH   640       // 20 warps: 10 m-positions x 2 h sub-tiles
#define NSTG  3         // cp.async pipeline stages

// __device__ scratch
__device__ __align__(16) __half g_xq3[(size_t)B_ * CIN * H_ * 3 * W_]; // pre-shifted acts
__device__ __align__(16) __half g_wh[(size_t)COUT * KTOT];             // weights [o][tap][ci]

// ---------------- helpers ----------------
__device__ __forceinline__ void cp_async16(uint32_t dst, const void* src, int nbytes) {
    asm volatile("cp.async.cg.shared.global [%0], [%1], 16, %2;\n"
                 :: "r"(dst), "l"(src), "r"(nbytes));
}
__device__ __forceinline__ void ldsm_x4(uint32_t* r, uint32_t addr) {
    asm volatile("ldmatrix.sync.aligned.m8n8.x4.shared.b16 {%0,%1,%2,%3}, [%4];"
                 : "=r"(r[0]), "=r"(r[1]), "=r"(r[2]), "=r"(r[3]) : "r"(addr));
}
__device__ __forceinline__ void ldsm_x4t(uint32_t* r, uint32_t addr) {
    asm volatile("ldmatrix.sync.aligned.m8n8.x4.trans.shared.b16 {%0,%1,%2,%3}, [%4];"
                 : "=r"(r[0]), "=r"(r[1]), "=r"(r[2]), "=r"(r[3]) : "r"(addr));
}
__device__ __forceinline__ void hmma(float* d, const uint32_t* a, const uint32_t* b) {
    asm volatile("mma.sync.aligned.m16n8k16.row.col.f32.f16.f16.f32 "
                 "{%0,%1,%2,%3}, {%4,%5,%6,%7}, {%8,%9}, {%0,%1,%2,%3};"
                 : "+f"(d[0]), "+f"(d[1]), "+f"(d[2]), "+f"(d[3])
                 : "r"(a[0]), "r"(a[1]), "r"(a[2]), "r"(a[3]), "r"(b[0]), "r"(b[1]));
}
// XOR swizzle for 128B rows: 16B chunk column ^ (row & 7)
__device__ __forceinline__ uint32_t swz(uint32_t row, uint32_t byte_in_row) {
    return row * 128 + (byte_in_row ^ ((row & 7) << 4));
}

// ---------------- Prep 1: quantize + 3-shift (fp16), one warp per (b,ci,h) row --------
__global__ void quant_kernel(const float* __restrict__ x,
                             const float* __restrict__ inv_p,
                             const float* __restrict__ zp_p)
{
    const float inv = inv_p[0];
    const float zp  = zp_p[0];
    int warp = (blockIdx.x * blockDim.x + threadIdx.x) >> 5;
    int lane = threadIdx.x & 31;
    if (warp >= B_ * CIN * H_) return;

    float2 v = reinterpret_cast<const float2*>(x + (size_t)warp * W_)[lane];
    float r0 = fminf(fmaxf(rintf(v.x * inv) + zp, -128.f), 127.f) - zp;
    float r1 = fminf(fmaxf(rintf(v.y * inv) + zp, -128.f), 127.f) - zp;
    __half2 h01 = __floats2half2_rn(r0, r1);
    uint32_t r = *reinterpret_cast<uint32_t*>(&h01);

    uint32_t prev = __shfl_up_sync(0xffffffffu, r, 1);
    uint32_t next = __shfl_down_sync(0xffffffffu, r, 1);
    if (lane == 0)  prev = 0;
    if (lane == 31) next = 0;
    uint32_t v0 = (prev >> 16) | (r << 16);   // kw=0 shift
    uint32_t v2 = (r >> 16) | (next << 16);   // kw=2 shift

    uint32_t* g32 = reinterpret_cast<uint32_t*>(g_xq3);
    size_t base = (size_t)warp * 96 + lane;
    g32[base]      = v0;
    g32[base + 32] = r;
    g32[base + 64] = v2;
}

// ---------------- Prep 2: weights i32 [O][Ci][3][3] -> fp16 [O][tap][Ci] -------------
__global__ void wreorder_kernel(const int* __restrict__ w)
{
    const int o  = blockIdx.x;
    const int ci = threadIdx.x;
    const int* src = w + ((size_t)o * CIN + ci) * 9;
    __half* dst = g_wh + (size_t)o * KTOT + ci;
    #pragma unroll
    for (int tap = 0; tap < 9; tap++)
        dst[tap * CIN] = __int2half_rn(src[tap]);
}

// ---------------- Main fp16 HMMA implicit-GEMM conv ----------------
static constexpr int A_STG = BM * 128;            // 40960
static constexpr int B_STG = S_ * 64 * 128;       // 16384
static constexpr int STG   = A_STG + B_STG;       // 57344
static constexpr int SMEM_TOTAL = NSTG * STG;     // 172032

__global__ __launch_bounds__(NTH, 1)
void conv_hmma_kernel(const float* __restrict__ scale,
                      const float* __restrict__ bias,
                      float* __restrict__ out)
{
    extern __shared__ __align__(128) unsigned char sm[];
    const uint32_t smb = (uint32_t)__cvta_generic_to_shared(sm);

    const int tid  = threadIdx.x;
    const int warp = tid >> 5;             // 0..19
    const int lane = tid & 31;
    const int wm   = (warp >> 1) * 32;     // 0..288
    const int ws   = warp & 1;             // h sub-tile

    const int b  = blockIdx.x >> 5;
    const int hg = (blockIdx.x & 31) * S_;

    float acc[2][8][4];
    #pragma unroll
    for (int mt = 0; mt < 2; mt++)
        #pragma unroll
        for (int nt = 0; nt < 8; nt++)
            #pragma unroll
            for (int r = 0; r < 4; r++)
                acc[mt][nt][r] = 0.f;

    auto load_stage = [&](int it) {
        const int kb  = it * BK;
        const int tap = kb / 320;
        const int cib = kb - tap * 320;
        const int kh  = tap / 3;
        const int kw  = tap - kh * 3;
        const uint32_t base = smb + (it % NSTG) * STG;
        // A: 320 rows x 128B  (2560 x 16B = 4 per thread)
        #pragma unroll
        for (int t = 0; t < 4; t++) {
            int idx = tid + t * NTH;
            int row = idx >> 3, vec = idx & 7;
            const void* src = g_wh + (size_t)row * KTOT + kb + vec * 8;
            cp_async16(base + swz(row, vec * 16), src, 16);
        }
        // B: 2 sub x 64 k-rows x 128B (1024 x 16B)
        #pragma unroll
        for (int t = 0; t < 2; t++) {
            int idx = tid + t * NTH;
            if (idx < 1024) {
                int ridx = idx >> 3, vec = idx & 7;
                int s = ridx >> 6, k = ridx & 63;
                int ci = cib + k;
                int ih = hg + s + kh - 1;
                int ok = ((unsigned)ih < (unsigned)H_) ? 16 : 0;
                if (!ok) ih = 0;
                const void* src = g_xq3 +
                    ((((size_t)b * CIN + ci) * H_ + ih) * 3 + kw) * W_ + vec * 8;
                cp_async16(base + A_STG + swz(s * 64 + k, vec * 16), src, ok);
            }
        }
        asm volatile("cp.async.commit_group;\n" ::: "memory");
    };

    load_stage(0);
    load_stage(1);

    const uint32_t a_row  = wm + (lane & 15);
    const uint32_t a_byte = (lane >> 4) * 16;
    const uint32_t b_krow = lane & 15;
    const uint32_t b_nby  = (lane >> 4) * 16;

    for (int it = 0; it < NKI; it++) {
        if (it + 1 < NKI) asm volatile("cp.async.wait_group 1;\n" ::: "memory");
        else              asm volatile("cp.async.wait_group 0;\n" ::: "memory");
        __syncthreads();
        if (it + 2 < NKI) load_stage(it + 2);

        const uint32_t Ab = smb + (it % NSTG) * STG;
        const uint32_t Bb = Ab + A_STG + ws * (64 * 128);
        #pragma unroll
        for (int ks = 0; ks < 4; ks++) {
            uint32_t a[2][4];
            #pragma unroll
            for (int mt = 0; mt < 2; mt++)
                ldsm_x4(a[mt], Ab + swz(a_row + mt * 16, ks * 32 + a_byte));
            #pragma unroll
            for (int ng = 0; ng < 4; ng++) {
                uint32_t bfrag[4];
                ldsm_x4t(bfrag, Bb + swz(ks * 16 + b_krow, ng * 32 + b_nby));
                #pragma unroll
                for (int mt = 0; mt < 2; mt++) {
                    hmma(acc[mt][ng * 2 + 0], a[mt], bfrag + 0);
                    hmma(acc[mt][ng * 2 + 1], a[mt], bfrag + 2);
                }
            }
        }
    }

    // ---------------- epilogue (direct fragment -> gmem) ----------------
    const int h = hg + ws;
    #pragma unroll
    for (int mt = 0; mt < 2; mt++) {
        const int o0 = wm + mt * 16 + (lane >> 2);
        const int o1 = o0 + 8;
        const float sc0 = scale[o0];
        const float sc1 = scale[o1];
        const float bb0 = bias[o0];
        const float bb1 = bias[o1];
        #pragma unroll
        for (int nt = 0; nt < 8; nt++) {
            const int w = nt * 8 + (lane & 3) * 2;
            float2 v0, v1;
            v0.x = sc0 * acc[mt][nt][0] + bb0;
            v0.y = sc0 * acc[mt][nt][1] + bb0;
            v1.x = sc1 * acc[mt][nt][2] + bb1;
            v1.y = sc1 * acc[mt][nt][3] + bb1;
            size_t p0 = (((size_t)b * COUT + o0) * H_ + h) * W_ + w;
            size_t p1 = (((size_t)b * COUT + o1) * H_ + h) * W_ + w;
            *reinterpret_cast<float2*>(out + p0) = v0;
            *reinterpret_cast<float2*>(out + p1) = v1;
        }
    }
}

// ---------------- Launch ----------------
// Inputs: 0:x f32  1:weight_int i32  2:weight_sum (unused)  3:scale f32
//         4:act_scales_inv f32  5:act_zero_points f32  6:bias f32 ; out f32
extern "C" void kernel_launch(void* const* d_in, const int* in_sizes, int n_in,
                              void* d_out, int out_size)
{
    const float* x    = (const float*)d_in[0];
    const int*   wint = (const int*)  d_in[1];
    const float* scl  = (const float*)d_in[3];
    const float* inv  = (const float*)d_in[4];
    const float* zp   = (const float*)d_in[5];
    const float* bias = (const float*)d_in[6];
    float* out = (float*)d_out;

    cudaFuncSetAttribute(conv_hmma_kernel,
                         cudaFuncAttributeMaxDynamicSharedMemorySize, SMEM_TOTAL);

    {   // quantize + pre-shift
        int rows = B_ * CIN * H_;
        quant_kernel<<<rows / 8, 256>>>(x, inv, zp);
    }
    {   // weights -> fp16, tap-major reorder
        wreorder_kernel<<<COUT, CIN>>>(wint);
    }
    {   // fp16 HMMA implicit GEMM
        conv_hmma_kernel<<<B_ * (H_ / S_), NTH, SMEM_TOTAL>>>(scl, bias, out);
    }
}